// round 5
// baseline (speedup 1.0000x reference)
#include <cuda_runtime.h>

// MKMMD loss, B=256, D=256, n=512, KERNEL_MUL=2, KERNEL_NUM=5, FIX_SIGMA=None.
// Single fused kernel: per-column stats + software grid barrier + loss.
// Final reduction in DOUBLE (the loss is a small difference of large group
// sums; float accumulation there loses ~3e-3 relative — measured in R4).
//
// Math:
//  - sum(l2_cum) over (n,n,D) = sum_f (D-f) * (2n*S2_f - 2*S1_f^2)
//  - only 4B=1024 (row,row) pairs contribute to the loss
//  - exp(-x/(bw_base*2^k)) = e4^(2^(4-k)) with e4 = exp(-x/(16*bw_base))

#define BB 256
#define DD 256
#define NROWS (2*BB)
#define WARPS_PER_BLOCK 8
#define NPAIRS (4*BB)
#define NBLOCKS (NPAIRS / WARPS_PER_BLOCK)   // 128 <= 148 SMs -> 1 wave, barrier-safe

__device__ float        g_s1[DD];            // per-column sums (atomic accum)
__device__ double       g_ws2;               // sum_f (D-f)*S2_f
__device__ double       g_part[NBLOCKS];     // per-block loss partials (double!)
__device__ unsigned int g_sync;              // grid barrier arrivals
__device__ unsigned int g_done;              // finalize arrivals

__global__ void __launch_bounds__(256, 1) mkmmd_fused_kernel(
    const float* __restrict__ src, const float* __restrict__ tgt,
    float* __restrict__ out) {
    const int tid  = threadIdx.x;
    const int warp = tid >> 5;
    const int lane = tid & 31;
    const int bid  = blockIdx.x;

    __shared__ float  sh_red[WARPS_PER_BLOCK];
    __shared__ double sh_redd[WARPS_PER_BLOCK];
    __shared__ float  sh_inv16;
    __shared__ bool   sh_final;

    // ---------------- pair setup: issue loads FIRST (overlap DRAM latency) ---
    const int p   = bid * WARPS_PER_BLOCK + warp;   // 0..1023
    const int grp = p >> 8;
    const int i   = p & (BB - 1);
    const int j   = (i + 1) & (BB - 1);

    const float* pa;
    const float* pb;
    float sign;
    if (grp == 0)      { pa = src + i * DD; pb = src + j * DD; sign =  1.f; }
    else if (grp == 1) { pa = tgt + i * DD; pb = tgt + j * DD; sign =  1.f; }
    else if (grp == 2) { pa = src + i * DD; pb = tgt + j * DD; sign = -1.f; }
    else               { pa = src + j * DD; pb = tgt + i * DD; sign = -1.f; }

    const float4* a4 = reinterpret_cast<const float4*>(pa) + lane * 2;
    const float4* b4 = reinterpret_cast<const float4*>(pb) + lane * 2;
    float4 a0 = a4[0], a1 = a4[1];
    float4 b0 = b4[0], b1 = b4[1];

    // ---------------- stats: block b owns rows 4b..4b+3, thread = column ----
    {
        const int r0 = bid * 4;
        float s1 = 0.f, s2 = 0.f;
#pragma unroll
        for (int k = 0; k < 4; ++k) {
            int r = r0 + k;
            const float* row = (r < BB) ? (src + r * DD) : (tgt + (r - BB) * DD);
            float v = row[tid];
            s1 += v;
            s2 = fmaf(v, v, s2);
        }
        atomicAdd(&g_s1[tid], s1);

        float term = (float)(DD - tid) * s2;
#pragma unroll
        for (int off = 16; off > 0; off >>= 1)
            term += __shfl_xor_sync(0xffffffffu, term, off);
        if (lane == 0) sh_red[warp] = term;
        __syncthreads();
        if (tid == 0) {
            float bsum = 0.f;
#pragma unroll
            for (int w = 0; w < WARPS_PER_BLOCK; ++w) bsum += sh_red[w];
            atomicAdd(&g_ws2, (double)bsum);
        }
    }

    // ---------------- diffs + prefix scan (independent of bandwidth) --------
    float sq[8];
    {
        float d0 = a0.x - b0.x, d1 = a0.y - b0.y, d2 = a0.z - b0.z, d3 = a0.w - b0.w;
        float d4 = a1.x - b1.x, d5 = a1.y - b1.y, d6 = a1.z - b1.z, d7 = a1.w - b1.w;
        sq[0] = d0 * d0; sq[1] = d1 * d1; sq[2] = d2 * d2; sq[3] = d3 * d3;
        sq[4] = d4 * d4; sq[5] = d5 * d5; sq[6] = d6 * d6; sq[7] = d7 * d7;
    }
    float run = 0.f;
#pragma unroll
    for (int k = 0; k < 8; ++k) { run += sq[k]; sq[k] = run; }

    float pref = run;
#pragma unroll
    for (int off = 1; off < 32; off <<= 1) {
        float y = __shfl_up_sync(0xffffffffu, pref, off);
        if (lane >= off) pref += y;
    }
    const float excl = pref - run;

    // ---------------- grid barrier (all stats atomics globally visible) -----
    __threadfence();
    __syncthreads();
    if (tid == 0) {
        unsigned int v = atomicAdd(&g_sync, 1u) + 1u;
        volatile unsigned int* sp = &g_sync;
        while (v < (unsigned int)NBLOCKS) v = *sp;
    }
    __syncthreads();
    __threadfence();

    // ---------------- bandwidth finalize (redundant per block) --------------
    {
        float s  = g_s1[tid];
        float tm = (float)(DD - tid) * s * s;
#pragma unroll
        for (int off = 16; off > 0; off >>= 1)
            tm += __shfl_xor_sync(0xffffffffu, tm, off);
        if (lane == 0) sh_red[warp] = tm;
        __syncthreads();
        if (tid == 0) {
            float s1sq = 0.f;
#pragma unroll
            for (int w = 0; w < WARPS_PER_BLOCK; ++w) s1sq += sh_red[w];
            const double n = (double)NROWS;
            double bwsum = 2.0 * n * g_ws2 - 2.0 * (double)s1sq;
            double bw    = bwsum / (n * n - n);
            sh_inv16 = (float)(1.0 / (4.0 * bw));   // 1/(16*bw_base)
        }
        __syncthreads();
    }
    const float inv16 = sh_inv16;

    // ---------------- multi-kernel Gaussian sum -----------------------------
    float lacc = 0.f;
#pragma unroll
    for (int k = 0; k < 8; ++k) {
        float y  = (sq[k] + excl) * inv16;
        float e4 = __expf(-y);               // exp(-x/(16 bb))
        float s  = e4;
        float t2 = e4 * e4;  s += t2;        // /8
        t2 *= t2;            s += t2;        // /4
        t2 *= t2;            s += t2;        // /2
        t2 *= t2;            s += t2;        // /1
        lacc += s;
    }

#pragma unroll
    for (int off = 16; off > 0; off >>= 1)
        lacc += __shfl_xor_sync(0xffffffffu, lacc, off);

    if (lane == 0) sh_red[warp] = lacc;
    __syncthreads();

    // ---------------- per-block partial -> distinct DOUBLE slot -------------
    if (tid == 0) {
        float bsum = 0.f;
#pragma unroll
        for (int w = 0; w < WARPS_PER_BLOCK; ++w) bsum += sh_red[w];
        g_part[bid] = (double)(sign * bsum);   // sign uniform within block
        __threadfence();
        unsigned int c = atomicAdd(&g_done, 1u);
        sh_final = (c == (unsigned int)(NBLOCKS - 1));
    }
    __syncthreads();

    // ---------------- last block: DOUBLE final sum + output + reset ---------
    if (sh_final) {
        __threadfence();
        double v = (tid < NBLOCKS) ? g_part[tid] : 0.0;
#pragma unroll
        for (int off = 16; off > 0; off >>= 1)
            v += __shfl_xor_sync(0xffffffffu, v, off);
        if (lane == 0) sh_redd[warp] = v;
        __syncthreads();
        if (tid == 0) {
            double total = 0.0;
#pragma unroll
            for (int w = 0; w < WARPS_PER_BLOCK; ++w) total += sh_redd[w];
            out[0] = (float)(total / (double)(BB * DD));
            g_ws2  = 0.0;
            g_sync = 0u;
            g_done = 0u;
        }
        g_s1[tid] = 0.f;
    }
}

extern "C" void kernel_launch(void* const* d_in, const int* in_sizes, int n_in,
                              void* d_out, int out_size) {
    const float* src = (const float*)d_in[0];
    const float* tgt = (const float*)d_in[1];
    float* out = (float*)d_out;
    (void)in_sizes; (void)n_in; (void)out_size;

    mkmmd_fused_kernel<<<NBLOCKS, 256>>>(src, tgt, out);
}

// round 6
// speedup vs baseline: 1.1950x; 1.1950x over previous
#include <cuda_runtime.h>

// MKMMD loss, B=256, D=256, n=512, KERNEL_MUL=2, KERNEL_NUM=5, FIX_SIGMA=None.
// Two kernels (boundary = free grid barrier). Stats accumulators padded to
// one 128B line per column to spread L2 atomic traffic across LTS slices.
//
// Math:
//  - sum(l2_cum) over (n,n,D) = sum_f (D-f) * (2n*S2_f - 2*S1_f^2)
//  - only 4B=1024 (row,row) pairs contribute to the loss
//  - exp(-x/(bw_base*2^k)) = e4^(2^(4-k)) with e4 = exp(-x/(16*bw_base))
//  - final 64-partial reduction in DOUBLE (float loses ~3e-3: measured R4)

#define BB 256
#define DD 256
#define NROWS (2*BB)
#define NPAIRS (4*BB)

#define K1_BLOCKS 64
#define K1_THREADS 256
#define ROWS_PER_BLOCK (NROWS / K1_BLOCKS)     // 8

#define K2_BLOCKS 64
#define K2_THREADS 512
#define K2_WARPS (K2_THREADS / 32)             // 16 pairs per block

#define PAD 32                                  // 32 floats = 128 B per column

__device__ float        g_s1p[DD * PAD];       // padded per-column sums
__device__ double       g_ws2;                 // sum_f (D-f)*S2_f
__device__ double       g_part[K2_BLOCKS];     // per-block loss partials
__device__ unsigned int g_done;

// ---------------------------------------------------------------------------
// Kernel 1: per-column stats. 64 blocks x 256 threads; block b owns 8 rows.
// ---------------------------------------------------------------------------
__global__ void __launch_bounds__(K1_THREADS, 1) stats_kernel(
    const float* __restrict__ src, const float* __restrict__ tgt) {
    const int t  = threadIdx.x;
    const int r0 = blockIdx.x * ROWS_PER_BLOCK;

    float s1 = 0.f, s2 = 0.f;
#pragma unroll
    for (int k = 0; k < ROWS_PER_BLOCK; ++k) {
        int r = r0 + k;
        const float* row = (r < BB) ? (src + r * DD) : (tgt + (r - BB) * DD);
        float v = row[t];
        s1 += v;
        s2 = fmaf(v, v, s2);
    }
    atomicAdd(&g_s1p[t * PAD], s1);            // distinct 128B line per column

    float term = (float)(DD - t) * s2;
#pragma unroll
    for (int off = 16; off > 0; off >>= 1)
        term += __shfl_xor_sync(0xffffffffu, term, off);

    __shared__ float wsum[K1_THREADS / 32];
    const int warp = t >> 5, lane = t & 31;
    if (lane == 0) wsum[warp] = term;
    __syncthreads();
    if (t == 0) {
        float bsum = 0.f;
#pragma unroll
        for (int w = 0; w < K1_THREADS / 32; ++w) bsum += wsum[w];
        atomicAdd(&g_ws2, (double)bsum);
    }
}

// ---------------------------------------------------------------------------
// Kernel 2: bandwidth finalize + loss. 64 blocks x 512 threads (16 pairs/blk).
// ---------------------------------------------------------------------------
__global__ void __launch_bounds__(K2_THREADS, 1) loss_kernel(
    const float* __restrict__ src, const float* __restrict__ tgt,
    float* __restrict__ out) {
    const int tid  = threadIdx.x;
    const int warp = tid >> 5;
    const int lane = tid & 31;
    const int bid  = blockIdx.x;

    __shared__ float  sh_red[K2_WARPS];
    __shared__ double sh_redd[2];
    __shared__ float  sh_inv16;
    __shared__ bool   sh_final;

    // ---- issue ALL global loads up front (overlap DRAM/L2 latency) ----
    const int p   = bid * K2_WARPS + warp;     // 0..1023; block spans one grp
    const int grp = p >> 8;
    const int i   = p & (BB - 1);
    const int j   = (i + 1) & (BB - 1);

    const float* pa;
    const float* pb;
    float sign;
    if (grp == 0)      { pa = src + i * DD; pb = src + j * DD; sign =  1.f; }
    else if (grp == 1) { pa = tgt + i * DD; pb = tgt + j * DD; sign =  1.f; }
    else if (grp == 2) { pa = src + i * DD; pb = tgt + j * DD; sign = -1.f; }
    else               { pa = src + j * DD; pb = tgt + i * DD; sign = -1.f; }

    const float4* a4 = reinterpret_cast<const float4*>(pa) + lane * 2;
    const float4* b4 = reinterpret_cast<const float4*>(pb) + lane * 2;
    float4 a0 = a4[0], a1 = a4[1];
    float4 b0 = b4[0], b1 = b4[1];
    float  sval = (tid < DD) ? g_s1p[tid * PAD] : 0.f;

    // ---- bandwidth finalize (per block; g_s1p complete via kernel boundary)
    {
        float tm = (float)(DD - tid) * sval * sval;   // 0 for tid>=DD
#pragma unroll
        for (int off = 16; off > 0; off >>= 1)
            tm += __shfl_xor_sync(0xffffffffu, tm, off);
        if (lane == 0) sh_red[warp] = tm;
        __syncthreads();
        if (tid == 0) {
            float s1sq = 0.f;
#pragma unroll
            for (int w = 0; w < K2_WARPS; ++w) s1sq += sh_red[w];
            const double n = (double)NROWS;
            double bwsum = 2.0 * n * g_ws2 - 2.0 * (double)s1sq;
            double bw    = bwsum / (n * n - n);
            sh_inv16 = (float)(1.0 / (4.0 * bw));     // 1/(16*bw_base)
        }
        __syncthreads();
    }
    const float inv16 = sh_inv16;

    // ---- squared diffs + in-lane prefix + warp exclusive scan ----
    float sq[8];
    {
        float d0 = a0.x - b0.x, d1 = a0.y - b0.y, d2 = a0.z - b0.z, d3 = a0.w - b0.w;
        float d4 = a1.x - b1.x, d5 = a1.y - b1.y, d6 = a1.z - b1.z, d7 = a1.w - b1.w;
        sq[0] = d0 * d0; sq[1] = d1 * d1; sq[2] = d2 * d2; sq[3] = d3 * d3;
        sq[4] = d4 * d4; sq[5] = d5 * d5; sq[6] = d6 * d6; sq[7] = d7 * d7;
    }
    float run = 0.f;
#pragma unroll
    for (int k = 0; k < 8; ++k) { run += sq[k]; sq[k] = run; }

    float pref = run;
#pragma unroll
    for (int off = 1; off < 32; off <<= 1) {
        float y = __shfl_up_sync(0xffffffffu, pref, off);
        if (lane >= off) pref += y;
    }
    const float excl = pref - run;

    // ---- multi-kernel Gaussian sum: 1 exp + 4 squarings ----
    float lacc = 0.f;
#pragma unroll
    for (int k = 0; k < 8; ++k) {
        float y  = (sq[k] + excl) * inv16;
        float e4 = __expf(-y);
        float s  = e4;
        float t2 = e4 * e4;  s += t2;
        t2 *= t2;            s += t2;
        t2 *= t2;            s += t2;
        t2 *= t2;            s += t2;
        lacc += s;
    }

#pragma unroll
    for (int off = 16; off > 0; off >>= 1)
        lacc += __shfl_xor_sync(0xffffffffu, lacc, off);

    if (lane == 0) sh_red[warp] = lacc;
    __syncthreads();

    // ---- per-block partial -> distinct double slot ----
    if (tid == 0) {
        float bsum = 0.f;
#pragma unroll
        for (int w = 0; w < K2_WARPS; ++w) bsum += sh_red[w];
        g_part[bid] = (double)(sign * bsum);
        __threadfence();
        unsigned int c = atomicAdd(&g_done, 1u);
        sh_final = (c == (unsigned int)(K2_BLOCKS - 1));
    }
    __syncthreads();

    // ---- last block: double reduce of 64 partials + output + reset ----
    if (sh_final) {
        __threadfence();
        double v = (tid < K2_BLOCKS) ? g_part[tid] : 0.0;
        if (tid < 64) {
#pragma unroll
            for (int off = 16; off > 0; off >>= 1)
                v += __shfl_xor_sync(0xffffffffu, v, off);
            if (lane == 0) sh_redd[warp] = v;
        }
        __syncthreads();
        if (tid == 0) {
            double total = sh_redd[0] + sh_redd[1];
            out[0] = (float)(total / (double)(BB * DD));
            g_ws2  = 0.0;
            g_done = 0u;
        }
        if (tid < DD) g_s1p[tid * PAD] = 0.f;   // reset for next graph replay
    }
}

extern "C" void kernel_launch(void* const* d_in, const int* in_sizes, int n_in,
                              void* d_out, int out_size) {
    const float* src = (const float*)d_in[0];
    const float* tgt = (const float*)d_in[1];
    float* out = (float*)d_out;
    (void)in_sizes; (void)n_in; (void)out_size;

    stats_kernel<<<K1_BLOCKS, K1_THREADS>>>(src, tgt);
    loss_kernel<<<K2_BLOCKS, K2_THREADS>>>(src, tgt, out);
}